// round 1
// baseline (speedup 1.0000x reference)
#include <cuda_runtime.h>

#define H 28
#define W 28
#define NSQ (H * W)          // 784 pixel nodes
#define OUTER NSQ            // node 784 = outer face, value +inf
#define NE_H (H * (W - 1))   // 756 horizontal interior edges
#define NE_V ((H - 1) * W)   // 756 vertical interior edges
#define NE_B (2 * H + 2 * W) // 112 boundary edges
#define NE (NE_H + NE_V + NE_B) // 1624
#define CARD 50

__global__ __launch_bounds__(1024, 1)
void cubical_kernel(const float* __restrict__ I, const float* __restrict__ p,
                    float* __restrict__ out) {
    __shared__ float Ip[NSQ];
    __shared__ float ew[NE];
    __shared__ short eu[NE];
    __shared__ short ev[NE];
    __shared__ short order[NE];
    __shared__ int   parent[NSQ + 1];
    __shared__ float cmax[NSQ + 1];
    __shared__ float pw[NSQ];   // pair birth (edge weight)
    __shared__ float pb[NSQ];   // pair death (component max)
    __shared__ int   npairs;

    const int t = threadIdx.x;
    const float p0 = p[0];
    const float p1 = p[1];

    // Phase 1: Ip = I . p  (28x28)
    for (int i = t; i < NSQ; i += blockDim.x)
        Ip[i] = fmaf(I[2 * i], p0, I[2 * i + 1] * p1);
    if (t <= NSQ) {
        parent[t] = t;
        cmax[t] = (t == OUTER) ? 1e30f : 0.0f;  // cmax[pixel] filled below
    }
    if (t == 0) npairs = 0;
    __syncthreads();
    if (t < NSQ) cmax[t] = Ip[t];

    // Phase 2: build edge list
    for (int i = t; i < NE; i += blockDim.x) {
        int u, v; float w;
        if (i < NE_H) {                       // horizontal: (r,c)-(r,c+1)
            int r = i / (W - 1), c = i % (W - 1);
            u = r * W + c; v = u + 1;
            w = fminf(Ip[u], Ip[v]);
        } else if (i < NE_H + NE_V) {         // vertical: (r,c)-(r+1,c)
            int j = i - NE_H;
            int r = j / W, c = j % W;
            u = r * W + c; v = u + W;
            w = fminf(Ip[u], Ip[v]);
        } else {                              // boundary edges -> OUTER
            int j = i - NE_H - NE_V;
            int sq;
            if (j < W)            sq = j;                       // top row
            else if (j < 2 * W)   sq = (H - 1) * W + (j - W);   // bottom row
            else if (j < 2 * W + H) sq = (j - 2 * W) * W;       // left col
            else                  sq = (j - 2 * W - H) * W + (W - 1); // right col
            u = sq; v = OUTER; w = Ip[sq];
        }
        eu[i] = (short)u; ev[i] = (short)v; ew[i] = w;
    }
    __syncthreads();

    // Phase 3: rank edges by (weight desc, index asc); unique ranks
    for (int i = t; i < NE; i += blockDim.x) {
        float wi = ew[i];
        int rank = 0;
        for (int j = 0; j < NE; j++) {
            float wj = ew[j];
            rank += (wj > wi) || (wj == wi && j < i);
        }
        order[rank] = (short)i;
    }
    __syncthreads();

    // Phase 4: sequential Kruskal (descending weight) with elder rule.
    // Superlevel H0 of the 4-connected pixel graph + outer node
    //   == sublevel H1 pairs (birth = edge weight, death = dying comp max).
    if (t == 0) {
        int np = 0;
        for (int k = 0; k < NE; k++) {
            int e = order[k];
            int a = eu[e], b = ev[e];
            // find with path halving
            for (;;) {
                int pa = parent[a];
                if (pa == a) break;
                int g = parent[pa];
                parent[a] = g;
                a = g;
            }
            for (;;) {
                int pb_ = parent[b];
                if (pb_ == b) break;
                int g = parent[pb_];
                parent[b] = g;
                b = g;
            }
            if (a == b) continue;
            float Ma = cmax[a], Mb = cmax[b];
            float w = ew[e];
            float die = fminf(Ma, Mb);
            if (die > w) { pw[np] = w; pb[np] = die; np++; }
            // surviving root keeps the larger max (outer = +inf stays root)
            if (Ma >= Mb) parent[b] = a;
            else          parent[a] = b;
        }
        npairs = np;
    }
    __syncthreads();

    // Phase 5: rank pairs by persistence descending (ref: argsort asc, reversed
    // -> among ties, larger original index first), emit top CARD, pad with Ip[0].
    const int np = npairs;
    for (int i = t; i < np; i += blockDim.x) {
        float pi = pb[i] - pw[i];
        int rank = 0;
        for (int j = 0; j < np; j++) {
            float pj = pb[j] - pw[j];
            rank += (pj > pi) || (pj == pi && j > i);
        }
        if (rank < CARD) {
            out[2 * rank]     = pw[i];
            out[2 * rank + 1] = pb[i];
        }
    }
    float pad = Ip[0];
    for (int k = t; k < CARD; k += blockDim.x) {
        if (k >= np) {
            out[2 * k]     = pad;
            out[2 * k + 1] = pad;
        }
    }
}

extern "C" void kernel_launch(void* const* d_in, const int* in_sizes, int n_in,
                              void* d_out, int out_size) {
    const float* I = (const float*)d_in[0];   // (28,28,2) float32
    const float* p = (const float*)d_in[1];   // (2,1) float32
    float* out = (float*)d_out;               // 100 float32
    (void)in_sizes; (void)n_in; (void)out_size;
    cubical_kernel<<<1, 1024>>>(I, p, out);
}